// round 3
// baseline (speedup 1.0000x reference)
#include <cuda_runtime.h>
#include <cstdint>

// Problem constants
#define N_SRC1  292864
#define N_DST1  11264
#define N_E1    281600
#define N_DST2  1024
#define N_E2    10240
#define IN_DIM  256
#define H_DIM   256
#define C_DIM   47

// Scratch (device globals — no allocation allowed)
// A = [x_dst | hneigh1] pre-split into tf32 hi/lo, [N_DST1 x 512]
__device__ float g_Ahi[N_DST1 * 512];
__device__ float g_Alo[N_DST1 * 512];
// W = [Wself1 ; Wneigh1] pre-split, [512 x 256]
__device__ float g_Whi[512 * 256];
__device__ float g_Wlo[512 * 256];
// relu(layer-1 output)
__device__ float g_h[N_DST1 * H_DIM];

// ---------------------------------------------------------------------------
// TF32 helpers
// ---------------------------------------------------------------------------
__device__ __forceinline__ uint32_t f2tf32(float f) {
    uint32_t r;
    asm("cvt.rna.tf32.f32 %0, %1;" : "=r"(r) : "f"(f));
    return r;
}
__device__ __forceinline__ void split_tf32(float v, float& hi, float& lo) {
    uint32_t h = f2tf32(v);
    hi = __uint_as_float(h);
    lo = __uint_as_float(f2tf32(v - hi));
}

__device__ __forceinline__ void mma_tf32(float c[4], const uint32_t a[4], const uint32_t b[2]) {
    asm volatile(
        "mma.sync.aligned.m16n8k8.row.col.f32.tf32.tf32.f32 "
        "{%0,%1,%2,%3}, {%4,%5,%6,%7}, {%8,%9}, {%0,%1,%2,%3};\n"
        : "+f"(c[0]), "+f"(c[1]), "+f"(c[2]), "+f"(c[3])
        : "r"(a[0]), "r"(a[1]), "r"(a[2]), "r"(a[3]), "r"(b[0]), "r"(b[1]));
}

// ---------------------------------------------------------------------------
// Layer-1 mean aggregation, fused with tf32 hi/lo split.
// One block per dst node (dst sorted). Writes A columns [256,512).
// ---------------------------------------------------------------------------
__global__ void agg1_cvt_kernel(const float* __restrict__ feat,
                                const int* __restrict__ src_idx,
                                const int* __restrict__ dst_idx,
                                float* __restrict__ Ahi,
                                float* __restrict__ Alo)
{
    const int d = blockIdx.x;

    int lo = 0, hi = N_E1;
    while (lo < hi) { int mid = (lo + hi) >> 1; if (__ldg(&dst_idx[mid]) < d) lo = mid + 1; else hi = mid; }
    const int start = lo;
    hi = N_E1;
    while (lo < hi) { int mid = (lo + hi) >> 1; if (__ldg(&dst_idx[mid]) <= d) lo = mid + 1; else hi = mid; }
    const int end = lo;

    const int t = threadIdx.x;           // 0..63
    float4 acc = make_float4(0.f, 0.f, 0.f, 0.f);

    for (int e = start; e < end; ++e) {
        const int s = __ldg(&src_idx[e]);
        const float4 v = *reinterpret_cast<const float4*>(&feat[(size_t)s * 256 + t * 4]);
        acc.x += v.x; acc.y += v.y; acc.z += v.z; acc.w += v.w;
    }

    const int deg = end - start;
    const float inv = (deg > 0) ? 1.0f / (float)deg : 0.0f;
    acc.x *= inv; acc.y *= inv; acc.z *= inv; acc.w *= inv;

    float4 vh, vl;
    split_tf32(acc.x, vh.x, vl.x);
    split_tf32(acc.y, vh.y, vl.y);
    split_tf32(acc.z, vh.z, vl.z);
    split_tf32(acc.w, vh.w, vl.w);
    const size_t off = (size_t)d * 512 + 256 + t * 4;
    *reinterpret_cast<float4*>(&Ahi[off]) = vh;
    *reinterpret_cast<float4*>(&Alo[off]) = vl;
}

// ---------------------------------------------------------------------------
// Pre-convert x[:11264] into A columns [0,256). One float4 per thread.
// ---------------------------------------------------------------------------
__global__ __launch_bounds__(256) void xconvert_kernel(const float* __restrict__ x,
                                                       float* __restrict__ Ahi,
                                                       float* __restrict__ Alo)
{
    const int idx = blockIdx.x * 256 + threadIdx.x;   // over 11264*64 float4s
    const int r  = idx >> 6;
    const int c4 = (idx & 63) * 4;
    const float4 v = *reinterpret_cast<const float4*>(&x[(size_t)r * 256 + c4]);
    float4 vh, vl;
    split_tf32(v.x, vh.x, vl.x);
    split_tf32(v.y, vh.y, vl.y);
    split_tf32(v.z, vh.z, vl.z);
    split_tf32(v.w, vh.w, vl.w);
    const size_t off = (size_t)r * 512 + c4;
    *reinterpret_cast<float4*>(&Ahi[off]) = vh;
    *reinterpret_cast<float4*>(&Alo[off]) = vl;
}

// ---------------------------------------------------------------------------
// Pre-convert stacked W = [Wself ; Wneigh] into Whi/Wlo [512 x 256].
// ---------------------------------------------------------------------------
__global__ __launch_bounds__(256) void wconvert_kernel(const float* __restrict__ Wself,
                                                       const float* __restrict__ Wneigh,
                                                       float* __restrict__ Whi,
                                                       float* __restrict__ Wlo)
{
    const int idx = blockIdx.x * 256 + threadIdx.x;   // over 512*64 float4s
    const int kk = idx >> 6;
    const int c4 = (idx & 63) * 4;
    const float* src = (kk < 256) ? &Wself[(size_t)kk * 256] : &Wneigh[(size_t)(kk - 256) * 256];
    const float4 v = *reinterpret_cast<const float4*>(&src[c4]);
    float4 vh, vl;
    split_tf32(v.x, vh.x, vl.x);
    split_tf32(v.y, vh.y, vl.y);
    split_tf32(v.z, vh.z, vl.z);
    split_tf32(v.w, vh.w, vl.w);
    const size_t off = (size_t)kk * 256 + c4;
    *reinterpret_cast<float4*>(&Whi[off]) = vh;
    *reinterpret_cast<float4*>(&Wlo[off]) = vl;
}

// ---------------------------------------------------------------------------
// Layer-1 GEMM (3xTF32 tensor core), pure-copy staging:
//   h = relu( A @ W + b ),  A [11264 x 512] (pre-split), W [512 x 256] (pre-split)
// CTA tile 128x64, BK=16, 8 warps (warp tile 64x16).
// ---------------------------------------------------------------------------
#define G1_BM 128
#define G1_BN 64
#define G1_BK 16
#define SA 136
#define SB 72

__global__ __launch_bounds__(256) void gemm1_tf32_kernel(
    const float* __restrict__ Ahi,
    const float* __restrict__ Alo,
    const float* __restrict__ Whi,
    const float* __restrict__ Wlo,
    const float* __restrict__ bias,     // [256]
    float* __restrict__ out)            // [N_DST1, 256]
{
    const int bx = blockIdx.x;          // 0..3   (N tiles of 64)
    const int by = blockIdx.y;          // 0..87  (M tiles of 128)

    const int tid  = threadIdx.x;
    const int warp = tid >> 5;
    const int lane = tid & 31;
    const int wm   = warp >> 2;         // 0..1
    const int wn   = warp & 3;          // 0..3
    const int g    = lane >> 2;         // 0..7
    const int tg   = lane & 3;          // 0..3

    __shared__ float As_hi[G1_BK * SA];
    __shared__ float As_lo[G1_BK * SA];
    __shared__ float Bs_hi[G1_BK * SB];
    __shared__ float Bs_lo[G1_BK * SB];

    float acc[4][2][4];
#pragma unroll
    for (int i = 0; i < 4; ++i)
#pragma unroll
        for (int j = 0; j < 2; ++j)
#pragma unroll
            for (int r = 0; r < 4; ++r) acc[i][j][r] = 0.f;

    // A staging: 128 rows x 16 k of hi+lo. 512 float4 slots / 256 thr = 2 each.
    const int a_row = tid >> 2;             // 0..63, second slot +64
    const int a_k   = (tid & 3) * 4;        // 0,4,8,12
    // B staging: 16 k x 64 n -> 256 float4 slots, 1 per thread.
    const int b_k   = tid >> 4;             // 0..15
    const int b_n   = (tid & 15) * 4;       // 0..60

    // Prefetch first tile
    float4 ah0, ah1, al0, al1, bh0, bl0;
    {
        const size_t ra = (size_t)(by * G1_BM + a_row) * 512 + a_k;
        const size_t rb = (size_t)(by * G1_BM + a_row + 64) * 512 + a_k;
        ah0 = *reinterpret_cast<const float4*>(&Ahi[ra]);
        al0 = *reinterpret_cast<const float4*>(&Alo[ra]);
        ah1 = *reinterpret_cast<const float4*>(&Ahi[rb]);
        al1 = *reinterpret_cast<const float4*>(&Alo[rb]);
        const size_t wb = (size_t)b_k * 256 + bx * G1_BN + b_n;
        bh0 = *reinterpret_cast<const float4*>(&Whi[wb]);
        bl0 = *reinterpret_cast<const float4*>(&Wlo[wb]);
    }

    for (int k0 = 0; k0 < 512; k0 += G1_BK) {
        // Store staged tile to shared (pure copy)
        {
            const float h0[4] = {ah0.x, ah0.y, ah0.z, ah0.w};
            const float l0[4] = {al0.x, al0.y, al0.z, al0.w};
            const float h1[4] = {ah1.x, ah1.y, ah1.z, ah1.w};
            const float l1[4] = {al1.x, al1.y, al1.z, al1.w};
#pragma unroll
            for (int j = 0; j < 4; ++j) {
                As_hi[(a_k + j) * SA + a_row]      = h0[j];
                As_lo[(a_k + j) * SA + a_row]      = l0[j];
                As_hi[(a_k + j) * SA + a_row + 64] = h1[j];
                As_lo[(a_k + j) * SA + a_row + 64] = l1[j];
            }
            *reinterpret_cast<float4*>(&Bs_hi[b_k * SB + b_n]) = bh0;
            *reinterpret_cast<float4*>(&Bs_lo[b_k * SB + b_n]) = bl0;
        }
        __syncthreads();

        // Prefetch next tile
        const int kn = k0 + G1_BK;
        if (kn < 512) {
            const size_t ra = (size_t)(by * G1_BM + a_row) * 512 + kn + a_k;
            const size_t rb = (size_t)(by * G1_BM + a_row + 64) * 512 + kn + a_k;
            ah0 = *reinterpret_cast<const float4*>(&Ahi[ra]);
            al0 = *reinterpret_cast<const float4*>(&Alo[ra]);
            ah1 = *reinterpret_cast<const float4*>(&Ahi[rb]);
            al1 = *reinterpret_cast<const float4*>(&Alo[rb]);
            const size_t wb = (size_t)(kn + b_k) * 256 + bx * G1_BN + b_n;
            bh0 = *reinterpret_cast<const float4*>(&Whi[wb]);
            bl0 = *reinterpret_cast<const float4*>(&Wlo[wb]);
        }

        // Two k-steps of 8
#pragma unroll
        for (int s = 0; s < 2; ++s) {
            uint32_t ahi[4][4], alo[4][4];
#pragma unroll
            for (int i = 0; i < 4; ++i) {
                const int m = wm * 64 + i * 16 + g;
                const int k = s * 8 + tg;
                ahi[i][0] = __float_as_uint(As_hi[k * SA + m]);
                ahi[i][1] = __float_as_uint(As_hi[k * SA + m + 8]);
                ahi[i][2] = __float_as_uint(As_hi[(k + 4) * SA + m]);
                ahi[i][3] = __float_as_uint(As_hi[(k + 4) * SA + m + 8]);
                alo[i][0] = __float_as_uint(As_lo[k * SA + m]);
                alo[i][1] = __float_as_uint(As_lo[k * SA + m + 8]);
                alo[i][2] = __float_as_uint(As_lo[(k + 4) * SA + m]);
                alo[i][3] = __float_as_uint(As_lo[(k + 4) * SA + m + 8]);
            }
            uint32_t bhi[2][2], blo[2][2];
#pragma unroll
            for (int j = 0; j < 2; ++j) {
                const int n = wn * 16 + j * 8 + g;
                const int k = s * 8 + tg;
                bhi[j][0] = __float_as_uint(Bs_hi[k * SB + n]);
                bhi[j][1] = __float_as_uint(Bs_hi[(k + 4) * SB + n]);
                blo[j][0] = __float_as_uint(Bs_lo[k * SB + n]);
                blo[j][1] = __float_as_uint(Bs_lo[(k + 4) * SB + n]);
            }
            // 3xTF32: lo*hi + hi*lo + hi*hi
#pragma unroll
            for (int i = 0; i < 4; ++i)
#pragma unroll
                for (int j = 0; j < 2; ++j) mma_tf32(acc[i][j], alo[i], bhi[j]);
#pragma unroll
            for (int i = 0; i < 4; ++i)
#pragma unroll
                for (int j = 0; j < 2; ++j) mma_tf32(acc[i][j], ahi[i], blo[j]);
#pragma unroll
            for (int i = 0; i < 4; ++i)
#pragma unroll
                for (int j = 0; j < 2; ++j) mma_tf32(acc[i][j], ahi[i], bhi[j]);
        }
        __syncthreads();
    }

    // Epilogue: +bias, relu, float2 stores
#pragma unroll
    for (int i = 0; i < 4; ++i) {
#pragma unroll
        for (int j = 0; j < 2; ++j) {
            const int col = bx * G1_BN + wn * 16 + j * 8 + tg * 2;
            const float bx0 = __ldg(&bias[col]);
            const float bx1 = __ldg(&bias[col + 1]);
            const int r0 = by * G1_BM + wm * 64 + i * 16 + g;
            float2 v0;
            v0.x = fmaxf(acc[i][j][0] + bx0, 0.f);
            v0.y = fmaxf(acc[i][j][1] + bx1, 0.f);
            *reinterpret_cast<float2*>(&out[(size_t)r0 * 256 + col]) = v0;
            float2 v1;
            v1.x = fmaxf(acc[i][j][2] + bx0, 0.f);
            v1.y = fmaxf(acc[i][j][3] + bx1, 0.f);
            *reinterpret_cast<float2*>(&out[(size_t)(r0 + 8) * 256 + col]) = v1;
        }
    }
}

// ---------------------------------------------------------------------------
// Fused layer 2: per output row d —
//   gather-mean neighbor h rows, then out[d] = h[d]@Ws + mean@Wn + b
// 1024 blocks x 128 threads.
// ---------------------------------------------------------------------------
__global__ __launch_bounds__(128) void layer2_fused_kernel(
    const float* __restrict__ h,        // [N_DST1, 256]
    const int* __restrict__ src2,
    const int* __restrict__ dst2,
    const float* __restrict__ Ws,       // [256, 47]
    const float* __restrict__ Wn,       // [256, 47]
    const float* __restrict__ bias,     // [47]
    float* __restrict__ out)            // [N_DST2, 47]
{
    const int d = blockIdx.x;

    int lo = 0, hi = N_E2;
    while (lo < hi) { int mid = (lo + hi) >> 1; if (__ldg(&dst2[mid]) < d) lo = mid + 1; else hi = mid; }
    const int start = lo;
    hi = N_E2;
    while (lo < hi) { int mid = (lo + hi) >> 1; if (__ldg(&dst2[mid]) <= d) lo = mid + 1; else hi = mid; }
    const int end = lo;

    __shared__ float a_self[256];
    __shared__ float a_nb[2][256];
    __shared__ float part[94];

    const int t    = threadIdx.x;
    const int half = t >> 6;            // 0/1 edge parity
    const int tt   = t & 63;            // float4 slice

    if (half == 0) {
        *reinterpret_cast<float4*>(&a_self[tt * 4]) =
            *reinterpret_cast<const float4*>(&h[(size_t)d * 256 + tt * 4]);
    }

    float4 acc = make_float4(0.f, 0.f, 0.f, 0.f);
    for (int e = start + half; e < end; e += 2) {
        const int s = __ldg(&src2[e]);
        const float4 v = *reinterpret_cast<const float4*>(&h[(size_t)s * 256 + tt * 4]);
        acc.x += v.x; acc.y += v.y; acc.z += v.z; acc.w += v.w;
    }
    *reinterpret_cast<float4*>(&a_nb[half][tt * 4]) = acc;
    __syncthreads();

    const int deg = end - start;
    const float inv = (deg > 0) ? 1.0f / (float)deg : 0.0f;
    if (half == 0) {
        float4 u = *reinterpret_cast<float4*>(&a_nb[0][tt * 4]);
        const float4 w = *reinterpret_cast<float4*>(&a_nb[1][tt * 4]);
        u.x = (u.x + w.x) * inv; u.y = (u.y + w.y) * inv;
        u.z = (u.z + w.z) * inv; u.w = (u.w + w.w) * inv;
        *reinterpret_cast<float4*>(&a_nb[0][tt * 4]) = u;
    }
    __syncthreads();

    // 94 threads: col c in [0,47), K split in halves of 128
    if (t < 94) {
        const int c  = (t < 47) ? t : t - 47;
        const int kb = (t < 47) ? 0 : 128;
        const float* as = &a_self[kb];
        const float* an = &a_nb[0][kb];
        float accS = 0.f, accN = 0.f;
#pragma unroll 8
        for (int k = 0; k < 128; ++k) {
            accS += as[k] * __ldg(&Ws[(size_t)(kb + k) * 47 + c]);
            accN += an[k] * __ldg(&Wn[(size_t)(kb + k) * 47 + c]);
        }
        part[t] = accS + accN;
    }
    __syncthreads();

    if (t < 47) {
        out[(size_t)d * 47 + t] = part[t] + part[t + 47] + __ldg(&bias[t]);
    }
}

// ---------------------------------------------------------------------------
// Launch
// ---------------------------------------------------------------------------
extern "C" void kernel_launch(void* const* d_in, const int* in_sizes, int n_in,
                              void* d_out, int out_size)
{
    const float* x       = (const float*)d_in[0];
    const int*   src1    = (const int*)  d_in[1];
    const int*   dst1    = (const int*)  d_in[2];
    const int*   src2    = (const int*)  d_in[3];
    const int*   dst2    = (const int*)  d_in[4];
    const float* Wself1  = (const float*)d_in[5];
    const float* Wneigh1 = (const float*)d_in[6];
    const float* b1      = (const float*)d_in[7];
    const float* Wself2  = (const float*)d_in[8];
    const float* Wneigh2 = (const float*)d_in[9];
    const float* b2      = (const float*)d_in[10];
    float* out = (float*)d_out;

    float* Ahi; cudaGetSymbolAddress((void**)&Ahi, g_Ahi);
    float* Alo; cudaGetSymbolAddress((void**)&Alo, g_Alo);
    float* Whi; cudaGetSymbolAddress((void**)&Whi, g_Whi);
    float* Wlo; cudaGetSymbolAddress((void**)&Wlo, g_Wlo);
    float* hbuf; cudaGetSymbolAddress((void**)&hbuf, g_h);

    // Independent prep: W split, x split, neighbor mean (+split)
    wconvert_kernel<<<(512 * 64) / 256, 256>>>(Wself1, Wneigh1, Whi, Wlo);
    xconvert_kernel<<<(N_DST1 * 64) / 256, 256>>>(x, Ahi, Alo);
    agg1_cvt_kernel<<<N_DST1, 64>>>(x, src1, dst1, Ahi, Alo);

    // Layer 1 GEMM + bias + relu (3xTF32 tensor core)
    dim3 g1(H_DIM / G1_BN, N_DST1 / G1_BM);   // (4, 88)
    gemm1_tf32_kernel<<<g1, 256>>>(Ahi, Alo, Whi, Wlo, b1, hbuf);

    // Fused layer 2 (agg + GEMM)
    layer2_fused_kernel<<<N_DST2, 128>>>(hbuf, src2, dst2, Wself2, Wneigh2, b2, out);
}

// round 4
// speedup vs baseline: 1.2203x; 1.2203x over previous
#include <cuda_runtime.h>
#include <cuda_bf16.h>
#include <cstdint>

// Problem constants
#define N_SRC1  292864
#define N_DST1  11264
#define N_E1    281600
#define N_DST2  1024
#define N_E2    10240
#define IN_DIM  256
#define H_DIM   256
#define C_DIM   47

// Scratch (device globals — no allocation allowed)
__device__ float g_hneigh1[N_DST1 * H_DIM];   // mean-aggregated neighbors, layer 1
__device__ float g_h[N_DST1 * H_DIM];         // relu(layer-1 output)

// ---------------------------------------------------------------------------
// Layer-1 mean aggregation: one block (128 thr) per dst node, 2-way edge split.
// ---------------------------------------------------------------------------
__global__ __launch_bounds__(128) void agg1_kernel(const float* __restrict__ feat,
                                                   const int* __restrict__ src_idx,
                                                   const int* __restrict__ dst_idx,
                                                   float* __restrict__ out)
{
    const int d = blockIdx.x;

    int lo = 0, hi = N_E1;
    while (lo < hi) { int mid = (lo + hi) >> 1; if (__ldg(&dst_idx[mid]) < d) lo = mid + 1; else hi = mid; }
    const int start = lo;
    hi = N_E1;
    while (lo < hi) { int mid = (lo + hi) >> 1; if (__ldg(&dst_idx[mid]) <= d) lo = mid + 1; else hi = mid; }
    const int end = lo;

    const int t    = threadIdx.x;
    const int half = t >> 6;            // 0/1 edge parity
    const int tt   = t & 63;            // float4 slice of the 256-dim row

    __shared__ float a_nb[2][256];

    float4 acc0 = make_float4(0.f, 0.f, 0.f, 0.f);
    float4 acc1 = make_float4(0.f, 0.f, 0.f, 0.f);

    int e = start + half;
    // 2x unrolled (stride 4 = 2 halves x unroll 2) for MLP
    for (; e + 2 < end; e += 4) {
        const int s0 = __ldg(&src_idx[e]);
        const int s1 = __ldg(&src_idx[e + 2]);
        const float4 v0 = *reinterpret_cast<const float4*>(&feat[(size_t)s0 * 256 + tt * 4]);
        const float4 v1 = *reinterpret_cast<const float4*>(&feat[(size_t)s1 * 256 + tt * 4]);
        acc0.x += v0.x; acc0.y += v0.y; acc0.z += v0.z; acc0.w += v0.w;
        acc1.x += v1.x; acc1.y += v1.y; acc1.z += v1.z; acc1.w += v1.w;
    }
    for (; e < end; e += 2) {
        const int s = __ldg(&src_idx[e]);
        const float4 v = *reinterpret_cast<const float4*>(&feat[(size_t)s * 256 + tt * 4]);
        acc0.x += v.x; acc0.y += v.y; acc0.z += v.z; acc0.w += v.w;
    }
    acc0.x += acc1.x; acc0.y += acc1.y; acc0.z += acc1.z; acc0.w += acc1.w;
    *reinterpret_cast<float4*>(&a_nb[half][tt * 4]) = acc0;
    __syncthreads();

    if (half == 0) {
        const int deg = end - start;
        const float inv = (deg > 0) ? 1.0f / (float)deg : 0.0f;
        float4 u = *reinterpret_cast<float4*>(&a_nb[0][tt * 4]);
        const float4 w = *reinterpret_cast<float4*>(&a_nb[1][tt * 4]);
        u.x = (u.x + w.x) * inv; u.y = (u.y + w.y) * inv;
        u.z = (u.z + w.z) * inv; u.w = (u.w + w.w) * inv;
        *reinterpret_cast<float4*>(&out[(size_t)d * 256 + tt * 4]) = u;
    }
}

// ---------------------------------------------------------------------------
// bf16 helpers
// ---------------------------------------------------------------------------
__device__ __forceinline__ void cvt_pack_bf16(float f0, float f1, uint32_t& hi, uint32_t& lo) {
    const __nv_bfloat16 h0 = __float2bfloat16_rn(f0);
    const __nv_bfloat16 h1 = __float2bfloat16_rn(f1);
    const float r0 = f0 - __bfloat162float(h0);
    const float r1 = f1 - __bfloat162float(h1);
    const __nv_bfloat16 l0 = __float2bfloat16_rn(r0);
    const __nv_bfloat16 l1 = __float2bfloat16_rn(r1);
    hi = (uint32_t)__bfloat16_as_ushort(h0) | ((uint32_t)__bfloat16_as_ushort(h1) << 16);
    lo = (uint32_t)__bfloat16_as_ushort(l0) | ((uint32_t)__bfloat16_as_ushort(l1) << 16);
}
__device__ __forceinline__ void cvt_bf16_pair(float f, __nv_bfloat16& h, __nv_bfloat16& l) {
    h = __float2bfloat16_rn(f);
    l = __float2bfloat16_rn(f - __bfloat162float(h));
}

__device__ __forceinline__ void mma_bf16(float c[4], const uint32_t a[4], const uint32_t b[2]) {
    asm volatile(
        "mma.sync.aligned.m16n8k16.row.col.f32.bf16.bf16.f32 "
        "{%0,%1,%2,%3}, {%4,%5,%6,%7}, {%8,%9}, {%0,%1,%2,%3};\n"
        : "+f"(c[0]), "+f"(c[1]), "+f"(c[2]), "+f"(c[3])
        : "r"(a[0]), "r"(a[1]), "r"(a[2]), "r"(a[3]), "r"(b[0]), "r"(b[1]));
}

// ---------------------------------------------------------------------------
// Layer-1 GEMM (3xBF16 hi/lo, m16n8k16):
//   h = relu( [x_dst | hneigh] @ [Wself ; Wneigh] + b )
// M=11264, N=256, K=512. CTA 128x64, BK=16, 8 warps, warp tile 32x32.
// Shared rows use 12-word (48B) stride: conflict-free for (12g+tg) frag loads.
// ---------------------------------------------------------------------------
#define G1_BM 128
#define G1_BN 64
#define G1_BK 16
#define SAW 12   // words per A row (16 bf16 = 8 words, padded to 12)
#define SBW 12   // words per B row

__global__ __launch_bounds__(256) void gemm1_bf16_kernel(
    const float* __restrict__ x,        // [N_SRC1, 256]
    const float* __restrict__ hneigh,   // [N_DST1, 256]
    const float* __restrict__ Wself,    // [256, 256]
    const float* __restrict__ Wneigh,   // [256, 256]
    const float* __restrict__ bias,     // [256]
    float* __restrict__ out)            // [N_DST1, 256]
{
    const int bx = blockIdx.x;          // 0..3   (N tiles of 64)
    const int by = blockIdx.y;          // 0..87  (M tiles of 128)

    const int tid  = threadIdx.x;
    const int warp = tid >> 5;
    const int lane = tid & 31;
    const int wm   = warp >> 1;         // 0..3  (32 rows each)
    const int wn   = warp & 1;          // 0..1  (32 cols each)
    const int g    = lane >> 2;         // 0..7
    const int tg   = lane & 3;          // 0..3

    __shared__ uint32_t As_hi[G1_BM * SAW];   // [m][k-words]
    __shared__ uint32_t As_lo[G1_BM * SAW];
    __shared__ uint32_t Bs_hi[G1_BN * SBW];   // [n][k-words]
    __shared__ uint32_t Bs_lo[G1_BN * SBW];

    float acc[2][4][4];
#pragma unroll
    for (int i = 0; i < 2; ++i)
#pragma unroll
        for (int j = 0; j < 4; ++j)
#pragma unroll
            for (int r = 0; r < 4; ++r) acc[i][j][r] = 0.f;

    // A staging map: thread -> (row, 8-k chunk)
    const int a_row = tid >> 1;             // 0..127
    const int a_kq  = (tid & 1) * 8;        // 0 or 8 (k offset)
    // B staging map: thread -> (k, 4-n chunk); note transpose on store
    const int b_k   = tid >> 4;             // 0..15
    const int b_n4  = (tid & 15) * 4;       // 0..60

    // Prefetch first tile (k0 = 0: A from x, W from Wself)
    float4 av0, av1, bv;
    {
        const size_t ar = (size_t)(by * G1_BM + a_row) * 256 + a_kq;
        av0 = *reinterpret_cast<const float4*>(&x[ar]);
        av1 = *reinterpret_cast<const float4*>(&x[ar + 4]);
        bv  = *reinterpret_cast<const float4*>(&Wself[(size_t)b_k * 256 + bx * G1_BN + b_n4]);
    }

    __nv_bfloat16* BsH = reinterpret_cast<__nv_bfloat16*>(Bs_hi);
    __nv_bfloat16* BsL = reinterpret_cast<__nv_bfloat16*>(Bs_lo);

    for (int k0 = 0; k0 < 512; k0 += G1_BK) {
        // ---- store staged tile to shared (convert to bf16 hi/lo) ----
        {
            const int w0 = a_kq >> 1;   // word base: 0 or 4
            uint32_t h, l;
            cvt_pack_bf16(av0.x, av0.y, h, l);
            As_hi[a_row * SAW + w0 + 0] = h; As_lo[a_row * SAW + w0 + 0] = l;
            cvt_pack_bf16(av0.z, av0.w, h, l);
            As_hi[a_row * SAW + w0 + 1] = h; As_lo[a_row * SAW + w0 + 1] = l;
            cvt_pack_bf16(av1.x, av1.y, h, l);
            As_hi[a_row * SAW + w0 + 2] = h; As_lo[a_row * SAW + w0 + 2] = l;
            cvt_pack_bf16(av1.z, av1.w, h, l);
            As_hi[a_row * SAW + w0 + 3] = h; As_lo[a_row * SAW + w0 + 3] = l;

            // B transpose: element (k=b_k, n=b_n4+c) -> Bs[n][k]
            const float bf[4] = {bv.x, bv.y, bv.z, bv.w};
#pragma unroll
            for (int c = 0; c < 4; ++c) {
                __nv_bfloat16 bh, bl;
                cvt_bf16_pair(bf[c], bh, bl);
                BsH[(b_n4 + c) * (SBW * 2) + b_k] = bh;
                BsL[(b_n4 + c) * (SBW * 2) + b_k] = bl;
            }
        }
        __syncthreads();

        // ---- prefetch next tile ----
        const int kn = k0 + G1_BK;
        if (kn < 512) {
            const float* Asrc = (kn < 256) ? x : hneigh;
            const float* Wsrc = (kn < 256) ? Wself : Wneigh;
            const int kk = kn & 255;
            const size_t ar = (size_t)(by * G1_BM + a_row) * 256 + kk + a_kq;
            av0 = *reinterpret_cast<const float4*>(&Asrc[ar]);
            av1 = *reinterpret_cast<const float4*>(&Asrc[ar + 4]);
            bv  = *reinterpret_cast<const float4*>(&Wsrc[(size_t)(kk + b_k) * 256 + bx * G1_BN + b_n4]);
        }

        // ---- fragments + MMAs (one k16 step) ----
        uint32_t Ah[2][4], Al[2][4], Bh[4][2], Bl[4][2];
#pragma unroll
        for (int i = 0; i < 2; ++i) {
            const int base = (wm * 32 + i * 16 + g) * SAW;
            Ah[i][0] = As_hi[base + tg];
            Ah[i][1] = As_hi[base + 8 * SAW + tg];
            Ah[i][2] = As_hi[base + tg + 4];
            Ah[i][3] = As_hi[base + 8 * SAW + tg + 4];
            Al[i][0] = As_lo[base + tg];
            Al[i][1] = As_lo[base + 8 * SAW + tg];
            Al[i][2] = As_lo[base + tg + 4];
            Al[i][3] = As_lo[base + 8 * SAW + tg + 4];
        }
#pragma unroll
        for (int j = 0; j < 4; ++j) {
            const int base = (wn * 32 + j * 8 + g) * SBW;
            Bh[j][0] = Bs_hi[base + tg];
            Bh[j][1] = Bs_hi[base + tg + 4];
            Bl[j][0] = Bs_lo[base + tg];
            Bl[j][1] = Bs_lo[base + tg + 4];
        }
        // 3xBF16: lo*hi + hi*lo + hi*hi (drop lo*lo)
#pragma unroll
        for (int i = 0; i < 2; ++i)
#pragma unroll
            for (int j = 0; j < 4; ++j) mma_bf16(acc[i][j], Al[i], Bh[j]);
#pragma unroll
        for (int i = 0; i < 2; ++i)
#pragma unroll
            for (int j = 0; j < 4; ++j) mma_bf16(acc[i][j], Ah[i], Bl[j]);
#pragma unroll
        for (int i = 0; i < 2; ++i)
#pragma unroll
            for (int j = 0; j < 4; ++j) mma_bf16(acc[i][j], Ah[i], Bh[j]);

        __syncthreads();
    }

    // Epilogue: +bias, relu, float2 stores
#pragma unroll
    for (int i = 0; i < 2; ++i) {
#pragma unroll
        for (int j = 0; j < 4; ++j) {
            const int col = bx * G1_BN + wn * 32 + j * 8 + tg * 2;
            const float b0 = __ldg(&bias[col]);
            const float b1 = __ldg(&bias[col + 1]);
            const int r0 = by * G1_BM + wm * 32 + i * 16 + g;
            float2 v0;
            v0.x = fmaxf(acc[i][j][0] + b0, 0.f);
            v0.y = fmaxf(acc[i][j][1] + b1, 0.f);
            *reinterpret_cast<float2*>(&out[(size_t)r0 * 256 + col]) = v0;
            float2 v1;
            v1.x = fmaxf(acc[i][j][2] + b0, 0.f);
            v1.y = fmaxf(acc[i][j][3] + b1, 0.f);
            *reinterpret_cast<float2*>(&out[(size_t)(r0 + 8) * 256 + col]) = v1;
        }
    }
}

// ---------------------------------------------------------------------------
// Fused layer 2: per output row d —
//   gather-mean neighbor h rows, then out[d] = h[d]@Ws + mean@Wn + b
// ---------------------------------------------------------------------------
__global__ __launch_bounds__(128) void layer2_fused_kernel(
    const float* __restrict__ h,        // [N_DST1, 256]
    const int* __restrict__ src2,
    const int* __restrict__ dst2,
    const float* __restrict__ Ws,       // [256, 47]
    const float* __restrict__ Wn,       // [256, 47]
    const float* __restrict__ bias,     // [47]
    float* __restrict__ out)            // [N_DST2, 47]
{
    const int d = blockIdx.x;

    int lo = 0, hi = N_E2;
    while (lo < hi) { int mid = (lo + hi) >> 1; if (__ldg(&dst2[mid]) < d) lo = mid + 1; else hi = mid; }
    const int start = lo;
    hi = N_E2;
    while (lo < hi) { int mid = (lo + hi) >> 1; if (__ldg(&dst2[mid]) <= d) lo = mid + 1; else hi = mid; }
    const int end = lo;

    __shared__ float a_self[256];
    __shared__ float a_nb[2][256];
    __shared__ float part[94];

    const int t    = threadIdx.x;
    const int half = t >> 6;
    const int tt   = t & 63;

    if (half == 0) {
        *reinterpret_cast<float4*>(&a_self[tt * 4]) =
            *reinterpret_cast<const float4*>(&h[(size_t)d * 256 + tt * 4]);
    }

    float4 acc = make_float4(0.f, 0.f, 0.f, 0.f);
    for (int e = start + half; e < end; e += 2) {
        const int s = __ldg(&src2[e]);
        const float4 v = *reinterpret_cast<const float4*>(&h[(size_t)s * 256 + tt * 4]);
        acc.x += v.x; acc.y += v.y; acc.z += v.z; acc.w += v.w;
    }
    *reinterpret_cast<float4*>(&a_nb[half][tt * 4]) = acc;
    __syncthreads();

    const int deg = end - start;
    const float inv = (deg > 0) ? 1.0f / (float)deg : 0.0f;
    if (half == 0) {
        float4 u = *reinterpret_cast<float4*>(&a_nb[0][tt * 4]);
        const float4 w = *reinterpret_cast<float4*>(&a_nb[1][tt * 4]);
        u.x = (u.x + w.x) * inv; u.y = (u.y + w.y) * inv;
        u.z = (u.z + w.z) * inv; u.w = (u.w + w.w) * inv;
        *reinterpret_cast<float4*>(&a_nb[0][tt * 4]) = u;
    }
    __syncthreads();

    if (t < 94) {
        const int c  = (t < 47) ? t : t - 47;
        const int kb = (t < 47) ? 0 : 128;
        const float* as = &a_self[kb];
        const float* an = &a_nb[0][kb];
        float accS = 0.f, accN = 0.f;
#pragma unroll 8
        for (int k = 0; k < 128; ++k) {
            accS += as[k] * __ldg(&Ws[(size_t)(kb + k) * 47 + c]);
            accN += an[k] * __ldg(&Wn[(size_t)(kb + k) * 47 + c]);
        }
        part[t] = accS + accN;
    }
    __syncthreads();

    if (t < 47) {
        out[(size_t)d * 47 + t] = part[t] + part[t + 47] + __ldg(&bias[t]);
    }
}

// ---------------------------------------------------------------------------
// Launch
// ---------------------------------------------------------------------------
extern "C" void kernel_launch(void* const* d_in, const int* in_sizes, int n_in,
                              void* d_out, int out_size)
{
    const float* x       = (const float*)d_in[0];
    const int*   src1    = (const int*)  d_in[1];
    const int*   dst1    = (const int*)  d_in[2];
    const int*   src2    = (const int*)  d_in[3];
    const int*   dst2    = (const int*)  d_in[4];
    const float* Wself1  = (const float*)d_in[5];
    const float* Wneigh1 = (const float*)d_in[6];
    const float* b1      = (const float*)d_in[7];
    const float* Wself2  = (const float*)d_in[8];
    const float* Wneigh2 = (const float*)d_in[9];
    const float* b2      = (const float*)d_in[10];
    float* out = (float*)d_out;

    float* hneigh1; cudaGetSymbolAddress((void**)&hneigh1, g_hneigh1);
    float* hbuf;    cudaGetSymbolAddress((void**)&hbuf,    g_h);

    // Layer 1: neighbor mean aggregation
    agg1_kernel<<<N_DST1, 128>>>(x, src1, dst1, hneigh1);

    // Layer 1: 3xBF16 tensor-core GEMM + bias + relu
    dim3 g1(H_DIM / G1_BN, N_DST1 / G1_BM);   // (4, 88)
    gemm1_bf16_kernel<<<g1, 256>>>(x, hneigh1, Wself1, Wneigh1, b1, hbuf);

    // Fused layer 2 (agg + GEMM)
    layer2_fused_kernel<<<N_DST2, 128>>>(hbuf, src2, dst2, Wself2, Wneigh2, b2, out);
}

// round 5
// speedup vs baseline: 1.4206x; 1.1641x over previous
#include <cuda_runtime.h>
#include <cuda_bf16.h>
#include <cstdint>

// Problem constants
#define N_SRC1  292864
#define N_DST1  11264
#define N_E1    281600
#define N_DST2  1024
#define N_E2    10240
#define IN_DIM  256
#define H_DIM   256
#define C_DIM   47

// Scratch (device globals — no allocation allowed)
// A = [x_dst | hneigh1] as bf16 hi/lo, [11264 x 512]
__device__ __nv_bfloat16 g_Ahi[N_DST1 * 512];
__device__ __nv_bfloat16 g_Alo[N_DST1 * 512];
// W^T = [Wself;Wneigh]^T as bf16 hi/lo, [256 n][512 k]
__device__ __nv_bfloat16 g_WThi[256 * 512];
__device__ __nv_bfloat16 g_WTlo[256 * 512];
// relu(layer-1 output)
__device__ float g_h[N_DST1 * H_DIM];

// ---------------------------------------------------------------------------
// bf16 split helpers
// ---------------------------------------------------------------------------
__device__ __forceinline__ uint32_t pack_bf16x2(float f0, float f1) {
    const __nv_bfloat16 b0 = __float2bfloat16_rn(f0);
    const __nv_bfloat16 b1 = __float2bfloat16_rn(f1);
    return (uint32_t)__bfloat16_as_ushort(b0) | ((uint32_t)__bfloat16_as_ushort(b1) << 16);
}
__device__ __forceinline__ void split4(float4 v, float4& hi, float4& lo) {
    hi.x = __bfloat162float(__float2bfloat16_rn(v.x)); lo.x = v.x - hi.x;
    hi.y = __bfloat162float(__float2bfloat16_rn(v.y)); lo.y = v.y - hi.y;
    hi.z = __bfloat162float(__float2bfloat16_rn(v.z)); lo.z = v.z - hi.z;
    hi.w = __bfloat162float(__float2bfloat16_rn(v.w)); lo.w = v.w - hi.w;
}
__device__ __forceinline__ void store_bf16x4(__nv_bfloat16* p, float4 v) {
    uint2 u;
    u.x = pack_bf16x2(v.x, v.y);
    u.y = pack_bf16x2(v.z, v.w);
    *reinterpret_cast<uint2*>(p) = u;
}

// ---------------------------------------------------------------------------
// Layer-1 mean aggregation: one block (64 thr) per dst node, 4x unroll.
// Emits bf16 hi/lo split directly into A columns [256,512).
// ---------------------------------------------------------------------------
__global__ __launch_bounds__(64) void agg1_kernel(const float* __restrict__ feat,
                                                  const int* __restrict__ src_idx,
                                                  const int* __restrict__ dst_idx,
                                                  __nv_bfloat16* __restrict__ Ahi,
                                                  __nv_bfloat16* __restrict__ Alo)
{
    const int d = blockIdx.x;

    int lo = 0, hi = N_E1;
    while (lo < hi) { int mid = (lo + hi) >> 1; if (__ldg(&dst_idx[mid]) < d) lo = mid + 1; else hi = mid; }
    const int start = lo;
    hi = N_E1;
    while (lo < hi) { int mid = (lo + hi) >> 1; if (__ldg(&dst_idx[mid]) <= d) lo = mid + 1; else hi = mid; }
    const int end = lo;

    const int t = threadIdx.x;          // 0..63, owns float4 slice

    float4 a0 = make_float4(0.f,0.f,0.f,0.f);
    float4 a1 = make_float4(0.f,0.f,0.f,0.f);
    float4 a2 = make_float4(0.f,0.f,0.f,0.f);
    float4 a3 = make_float4(0.f,0.f,0.f,0.f);

    int e = start;
    for (; e + 3 < end; e += 4) {
        const int s0 = __ldg(&src_idx[e]);
        const int s1 = __ldg(&src_idx[e + 1]);
        const int s2 = __ldg(&src_idx[e + 2]);
        const int s3 = __ldg(&src_idx[e + 3]);
        const float4 v0 = *reinterpret_cast<const float4*>(&feat[(size_t)s0 * 256 + t * 4]);
        const float4 v1 = *reinterpret_cast<const float4*>(&feat[(size_t)s1 * 256 + t * 4]);
        const float4 v2 = *reinterpret_cast<const float4*>(&feat[(size_t)s2 * 256 + t * 4]);
        const float4 v3 = *reinterpret_cast<const float4*>(&feat[(size_t)s3 * 256 + t * 4]);
        a0.x += v0.x; a0.y += v0.y; a0.z += v0.z; a0.w += v0.w;
        a1.x += v1.x; a1.y += v1.y; a1.z += v1.z; a1.w += v1.w;
        a2.x += v2.x; a2.y += v2.y; a2.z += v2.z; a2.w += v2.w;
        a3.x += v3.x; a3.y += v3.y; a3.z += v3.z; a3.w += v3.w;
    }
    for (; e < end; ++e) {
        const int s = __ldg(&src_idx[e]);
        const float4 v = *reinterpret_cast<const float4*>(&feat[(size_t)s * 256 + t * 4]);
        a0.x += v.x; a0.y += v.y; a0.z += v.z; a0.w += v.w;
    }
    a0.x += a1.x + a2.x + a3.x;
    a0.y += a1.y + a2.y + a3.y;
    a0.z += a1.z + a2.z + a3.z;
    a0.w += a1.w + a2.w + a3.w;

    const int deg = end - start;
    const float inv = (deg > 0) ? 1.0f / (float)deg : 0.0f;
    a0.x *= inv; a0.y *= inv; a0.z *= inv; a0.w *= inv;

    float4 vh, vl;
    split4(a0, vh, vl);
    const size_t off = (size_t)d * 512 + 256 + t * 4;
    store_bf16x4(&Ahi[off], vh);
    store_bf16x4(&Alo[off], vl);
}

// ---------------------------------------------------------------------------
// Convert x[:11264] into A columns [0,256) (bf16 hi/lo).
// ---------------------------------------------------------------------------
__global__ __launch_bounds__(256) void xcvt_kernel(const float* __restrict__ x,
                                                   __nv_bfloat16* __restrict__ Ahi,
                                                   __nv_bfloat16* __restrict__ Alo)
{
    const int idx = blockIdx.x * 256 + threadIdx.x;   // 11264*64 float4s
    const int r  = idx >> 6;
    const int c4 = (idx & 63) * 4;
    const float4 v = *reinterpret_cast<const float4*>(&x[(size_t)r * 256 + c4]);
    float4 vh, vl;
    split4(v, vh, vl);
    const size_t off = (size_t)r * 512 + c4;
    store_bf16x4(&Ahi[off], vh);
    store_bf16x4(&Alo[off], vl);
}

// ---------------------------------------------------------------------------
// Transpose + convert W: WT[n][k] = (k<256 ? Wself[k][n] : Wneigh[k-256][n])
// ---------------------------------------------------------------------------
__global__ __launch_bounds__(256) void wcvt_kernel(const float* __restrict__ Wself,
                                                   const float* __restrict__ Wneigh,
                                                   __nv_bfloat16* __restrict__ WThi,
                                                   __nv_bfloat16* __restrict__ WTlo)
{
    const int idx = blockIdx.x * 256 + threadIdx.x;   // 256*512 elems
    const int n = idx >> 9;
    const int k = idx & 511;
    const float v = (k < 256) ? __ldg(&Wself[(size_t)k * 256 + n])
                              : __ldg(&Wneigh[(size_t)(k - 256) * 256 + n]);
    const float h = __bfloat162float(__float2bfloat16_rn(v));
    WThi[(size_t)n * 512 + k] = __float2bfloat16_rn(v);
    WTlo[(size_t)n * 512 + k] = __float2bfloat16_rn(v - h);
}

// ---------------------------------------------------------------------------
// cp.async / ldmatrix helpers
// ---------------------------------------------------------------------------
__device__ __forceinline__ void cp_async16(uint32_t saddr, const void* g) {
    asm volatile("cp.async.ca.shared.global [%0], [%1], 16;\n" :: "r"(saddr), "l"(g));
}
__device__ __forceinline__ void cp_commit() {
    asm volatile("cp.async.commit_group;\n" ::: "memory");
}
__device__ __forceinline__ void cp_wait0() {
    asm volatile("cp.async.wait_group 0;\n" ::: "memory");
}
__device__ __forceinline__ void ldsm_x4(uint32_t& r0, uint32_t& r1, uint32_t& r2, uint32_t& r3,
                                        uint32_t addr) {
    asm volatile("ldmatrix.sync.aligned.m8n8.x4.shared.b16 {%0,%1,%2,%3}, [%4];\n"
                 : "=r"(r0), "=r"(r1), "=r"(r2), "=r"(r3) : "r"(addr));
}
__device__ __forceinline__ void mma_bf16(float c[4], const uint32_t a[4], const uint32_t b[2]) {
    asm volatile(
        "mma.sync.aligned.m16n8k16.row.col.f32.bf16.bf16.f32 "
        "{%0,%1,%2,%3}, {%4,%5,%6,%7}, {%8,%9}, {%0,%1,%2,%3};\n"
        : "+f"(c[0]), "+f"(c[1]), "+f"(c[2]), "+f"(c[3])
        : "r"(a[0]), "r"(a[1]), "r"(a[2]), "r"(a[3]), "r"(b[0]), "r"(b[1]));
}

// ---------------------------------------------------------------------------
// Layer-1 GEMM: h = relu(A @ WT^T + b), 3xBF16 hi/lo via mma.m16n8k16.
// A [11264 x 512] bf16 (hi/lo), WT [256 x 512] bf16 (hi/lo).
// CTA 128x64, BK=16, 8 warps (warp 32x32), cp.async double buffer + ldmatrix.
// Shared rows: 12-word (48B) stride -> conflict-free LDSM phases.
// ---------------------------------------------------------------------------
#define G1_BM 128
#define G1_BN 64
#define SAW 12
// word offsets within a stage
#define OFF_AH 0
#define OFF_AL (G1_BM * SAW)                // 1536
#define OFF_BH (2 * G1_BM * SAW)            // 3072
#define OFF_BL (2 * G1_BM * SAW + G1_BN * SAW)  // 3840
#define STAGE_WORDS (2 * G1_BM * SAW + 2 * G1_BN * SAW)  // 4608

__global__ __launch_bounds__(256) void gemm1_kernel(
    const __nv_bfloat16* __restrict__ Ahi,
    const __nv_bfloat16* __restrict__ Alo,
    const __nv_bfloat16* __restrict__ WThi,
    const __nv_bfloat16* __restrict__ WTlo,
    const float* __restrict__ bias,
    float* __restrict__ out)
{
    const int bx = blockIdx.x;          // 0..3
    const int by = blockIdx.y;          // 0..87

    const int tid  = threadIdx.x;
    const int warp = tid >> 5;
    const int lane = tid & 31;
    const int wm   = warp >> 1;         // 0..3
    const int wn   = warp & 1;          // 0..1
    const int g    = lane >> 2;
    const int tg   = lane & 3;

    __shared__ __align__(16) uint32_t smem[2 * STAGE_WORDS];

    uint32_t sbase;
    asm("{ .reg .u64 t; cvta.to.shared.u64 t, %1; cvt.u32.u64 %0, t; }"
        : "=r"(sbase) : "l"(smem));

    // ---- cp.async staging maps ----
    // A: 128 rows x 2 chunks; each thread: 1 (row,chunk) for hi and lo.
    const int a_row = tid >> 1;
    const int a_ch  = tid & 1;
    // B: 64 rows x 2 chunks x {hi,lo}: 256 ops, 1 per thread.
    const int b_arr = tid >> 7;         // 0 = hi, 1 = lo
    const int b_row = (tid & 127) >> 1;
    const int b_ch  = tid & 1;

    const __nv_bfloat16* gA_hi = Ahi + (size_t)(by * G1_BM + a_row) * 512 + a_ch * 8;
    const __nv_bfloat16* gA_lo = Alo + (size_t)(by * G1_BM + a_row) * 512 + a_ch * 8;
    const __nv_bfloat16* gB    = (b_arr ? WTlo : WThi) + (size_t)(bx * G1_BN + b_row) * 512 + b_ch * 8;

    const uint32_t sA_hi = sbase + (OFF_AH + a_row * SAW + a_ch * 4) * 4;
    const uint32_t sA_lo = sbase + (OFF_AL + a_row * SAW + a_ch * 4) * 4;
    const uint32_t sB    = sbase + ((b_arr ? OFF_BL : OFF_BH) + b_row * SAW + b_ch * 4) * 4;

    // ---- ldmatrix address maps (stage 0) ----
    // A tile i: rows wm*32+i*16 + (lane&15), word (lane>>4)*4
    uint32_t aAddr[2];
#pragma unroll
    for (int i = 0; i < 2; ++i) {
        const int row = wm * 32 + i * 16 + (lane & 15);
        const int word = (lane >> 4) * 4;
        aAddr[i] = sbase + (OFF_AH + row * SAW + word) * 4;
    }
    // B pair p: rows wn*32+p*16 + (lane&7) + ((lane>>4)<<3), word ((lane>>3)&1)*4
    uint32_t bAddr[2];
#pragma unroll
    for (int p = 0; p < 2; ++p) {
        const int row = wn * 32 + p * 16 + (lane & 7) + ((lane >> 4) << 3);
        const int word = ((lane >> 3) & 1) * 4;
        bAddr[p] = sbase + (OFF_BH + row * SAW + word) * 4;
    }
    const uint32_t stage_bytes = STAGE_WORDS * 4;
    const uint32_t AL_off = (OFF_AL - OFF_AH) * 4;   // hi -> lo (A)
    const uint32_t BL_off = (OFF_BL - OFF_BH) * 4;   // hi -> lo (B)

    float acc[2][4][4];
#pragma unroll
    for (int i = 0; i < 2; ++i)
#pragma unroll
        for (int j = 0; j < 4; ++j)
#pragma unroll
            for (int r = 0; r < 4; ++r) acc[i][j][r] = 0.f;

    // ---- prologue: stage 0 = k-tile 0 ----
    cp_async16(sA_hi, gA_hi);
    cp_async16(sA_lo, gA_lo);
    cp_async16(sB,    gB);
    cp_commit();

    for (int t = 0; t < 32; ++t) {
        cp_wait0();
        __syncthreads();

        // issue next tile into the other stage (safe: everyone passed the barrier)
        if (t + 1 < 32) {
            const int kn = (t + 1) * 16;
            const uint32_t so = ((t + 1) & 1) * stage_bytes;
            cp_async16(sA_hi + so, gA_hi + kn);
            cp_async16(sA_lo + so, gA_lo + kn);
            cp_async16(sB + so,    gB + kn);
            cp_commit();
        }

        // fragments
        const uint32_t so = (t & 1) * stage_bytes;
        uint32_t Ah[2][4], Al[2][4], Bh[2][4], Bl[2][4];
#pragma unroll
        for (int i = 0; i < 2; ++i) {
            ldsm_x4(Ah[i][0], Ah[i][1], Ah[i][2], Ah[i][3], aAddr[i] + so);
            ldsm_x4(Al[i][0], Al[i][1], Al[i][2], Al[i][3], aAddr[i] + so + AL_off);
        }
#pragma unroll
        for (int p = 0; p < 2; ++p) {
            ldsm_x4(Bh[p][0], Bh[p][1], Bh[p][2], Bh[p][3], bAddr[p] + so);
            ldsm_x4(Bl[p][0], Bl[p][1], Bl[p][2], Bl[p][3], bAddr[p] + so + BL_off);
        }

        // 3xBF16: lo*hi + hi*lo + hi*hi
#pragma unroll
        for (int i = 0; i < 2; ++i)
#pragma unroll
            for (int j = 0; j < 4; ++j) {
                const uint32_t bfrag[2] = { Bh[j >> 1][(j & 1) * 2], Bh[j >> 1][(j & 1) * 2 + 1] };
                mma_bf16(acc[i][j], Al[i], bfrag);
            }
#pragma unroll
        for (int i = 0; i < 2; ++i)
#pragma unroll
            for (int j = 0; j < 4; ++j) {
                const uint32_t bfrag[2] = { Bl[j >> 1][(j & 1) * 2], Bl[j >> 1][(j & 1) * 2 + 1] };
                mma_bf16(acc[i][j], Ah[i], bfrag);
            }
#pragma unroll
        for (int i = 0; i < 2; ++i)
#pragma unroll
            for (int j = 0; j < 4; ++j) {
                const uint32_t bfrag[2] = { Bh[j >> 1][(j & 1) * 2], Bh[j >> 1][(j & 1) * 2 + 1] };
                mma_bf16(acc[i][j], Ah[i], bfrag);
            }
    }

    // Epilogue: +bias, relu, float2 stores
#pragma unroll
    for (int i = 0; i < 2; ++i) {
#pragma unroll
        for (int j = 0; j < 4; ++j) {
            const int col = bx * G1_BN + wn * 32 + j * 8 + tg * 2;
            const float b0 = __ldg(&bias[col]);
            const float b1 = __ldg(&bias[col + 1]);
            const int r0 = by * G1_BM + wm * 32 + i * 16 + g;
            float2 v0;
            v0.x = fmaxf(acc[i][j][0] + b0, 0.f);
            v0.y = fmaxf(acc[i][j][1] + b1, 0.f);
            *reinterpret_cast<float2*>(&out[(size_t)r0 * 256 + col]) = v0;
            float2 v1;
            v1.x = fmaxf(acc[i][j][2] + b0, 0.f);
            v1.y = fmaxf(acc[i][j][3] + b1, 0.f);
            *reinterpret_cast<float2*>(&out[(size_t)(r0 + 8) * 256 + col]) = v1;
        }
    }
}

// ---------------------------------------------------------------------------
// Fused layer 2: gather-mean + tiny GEMM per output row.
// ---------------------------------------------------------------------------
__global__ __launch_bounds__(128) void layer2_fused_kernel(
    const float* __restrict__ h,
    const int* __restrict__ src2,
    const int* __restrict__ dst2,
    const float* __restrict__ Ws,
    const float* __restrict__ Wn,
    const float* __restrict__ bias,
    float* __restrict__ out)
{
    const int d = blockIdx.x;

    int lo = 0, hi = N_E2;
    while (lo < hi) { int mid = (lo + hi) >> 1; if (__ldg(&dst2[mid]) < d) lo = mid + 1; else hi = mid; }
    const int start = lo;
    hi = N_E2;
    while (lo < hi) { int mid = (lo + hi) >> 1; if (__ldg(&dst2[mid]) <= d) lo = mid + 1; else hi = mid; }
    const int end = lo;

    __shared__ float a_self[256];
    __shared__ float a_nb[2][256];
    __shared__ float part[94];

    const int t    = threadIdx.x;
    const int half = t >> 6;
    const int tt   = t & 63;

    if (half == 0) {
        *reinterpret_cast<float4*>(&a_self[tt * 4]) =
            *reinterpret_cast<const float4*>(&h[(size_t)d * 256 + tt * 4]);
    }

    float4 acc = make_float4(0.f, 0.f, 0.f, 0.f);
    for (int e = start + half; e < end; e += 2) {
        const int s = __ldg(&src2[e]);
        const float4 v = *reinterpret_cast<const float4*>(&h[(size_t)s * 256 + tt * 4]);
        acc.x += v.x; acc.y += v.y; acc.z += v.z; acc.w += v.w;
    }
    *reinterpret_cast<float4*>(&a_nb[half][tt * 4]) = acc;
    __syncthreads();

    const int deg = end - start;
    const float inv = (deg > 0) ? 1.0f / (float)deg : 0.0f;
    if (half == 0) {
        float4 u = *reinterpret_cast<float4*>(&a_nb[0][tt * 4]);
        const float4 w = *reinterpret_cast<float4*>(&a_nb[1][tt * 4]);
        u.x = (u.x + w.x) * inv; u.y = (u.y + w.y) * inv;
        u.z = (u.z + w.z) * inv; u.w = (u.w + w.w) * inv;
        *reinterpret_cast<float4*>(&a_nb[0][tt * 4]) = u;
    }
    __syncthreads();

    if (t < 94) {
        const int c  = (t < 47) ? t : t - 47;
        const int kb = (t < 47) ? 0 : 128;
        const float* as = &a_self[kb];
        const float* an = &a_nb[0][kb];
        float accS = 0.f, accN = 0.f;
#pragma unroll 8
        for (int k = 0; k < 128; ++k) {
            accS += as[k] * __ldg(&Ws[(size_t)(kb + k) * 47 + c]);
            accN += an[k] * __ldg(&Wn[(size_t)(kb + k) * 47 + c]);
        }
        part[t] = accS + accN;
    }
    __syncthreads();

    if (t < 47) {
        out[(size_t)d * 47 + t] = part[t] + part[t + 47] + __ldg(&bias[t]);
    }
}

// ---------------------------------------------------------------------------
// Launch
// ---------------------------------------------------------------------------
extern "C" void kernel_launch(void* const* d_in, const int* in_sizes, int n_in,
                              void* d_out, int out_size)
{
    const float* x       = (const float*)d_in[0];
    const int*   src1    = (const int*)  d_in[1];
    const int*   dst1    = (const int*)  d_in[2];
    const int*   src2    = (const int*)  d_in[3];
    const int*   dst2    = (const int*)  d_in[4];
    const float* Wself1  = (const float*)d_in[5];
    const float* Wneigh1 = (const float*)d_in[6];
    const float* b1      = (const float*)d_in[7];
    const float* Wself2  = (const float*)d_in[8];
    const float* Wneigh2 = (const float*)d_in[9];
    const float* b2      = (const float*)d_in[10];
    float* out = (float*)d_out;

    __nv_bfloat16 *Ahi, *Alo, *WThi, *WTlo;
    float* hbuf;
    cudaGetSymbolAddress((void**)&Ahi,  g_Ahi);
    cudaGetSymbolAddress((void**)&Alo,  g_Alo);
    cudaGetSymbolAddress((void**)&WThi, g_WThi);
    cudaGetSymbolAddress((void**)&WTlo, g_WTlo);
    cudaGetSymbolAddress((void**)&hbuf, g_h);

    // Prep: W transpose+convert, x convert, neighbor mean (+convert)
    wcvt_kernel<<<(256 * 512) / 256, 256>>>(Wself1, Wneigh1, WThi, WTlo);
    xcvt_kernel<<<(N_DST1 * 64) / 256, 256>>>(x, Ahi, Alo);
    agg1_kernel<<<N_DST1, 64>>>(x, src1, dst1, Ahi, Alo);

    // Layer 1 GEMM + bias + relu
    dim3 g1(H_DIM / G1_BN, N_DST1 / G1_BM);   // (4, 88)
    gemm1_kernel<<<g1, 256>>>(Ahi, Alo, WThi, WTlo, b1, hbuf);

    // Fused layer 2
    layer2_fused_kernel<<<N_DST2, 128>>>(hbuf, src2, dst2, Wself2, Wneigh2, b2, out);
}